// round 14
// baseline (speedup 1.0000x reference)
#include <cuda_runtime.h>
#include <cuda_bf16.h>
#include <cstdint>

// ---------------------------------------------------------------------------
// HebbianMap2d: y_out = relu(conv(x,w)); new_w = w + eta*(r^T Xu - tril(r^T r) W)/N
// with r = lfb(winner(relu(s))) * relu(s).
// Shapes: x[32,3,64,64], w[256,3,5,5] -> y_out[32,256,60,60], new_w[256,75]
// NOTE: toolchain targets sm_100 (no 'a') -> tcgen05 unavailable; mma.sync only.
// ---------------------------------------------------------------------------

#define B_    32
#define C_    3
#define H_    64
#define W_    64
#define HO_   60
#define WO_   60
#define HW_   3600          // 60*60
#define O_    256
#define D_    75            // 3*5*5
#define DP    80            // D padded to multiple of 16
#define NTOT  115200        // 32*3600
#define YOUT  29491200      // 32*256*3600
#define ZB    59            // ragged split-K: 30 z's get 31 iters, 29 get 30 (x64)

// ------------------------- scratch (device globals) ------------------------
__device__ __align__(16) float g_K[O_ * O_];                 // SOM lateral kernel
__device__ __align__(16) __nv_bfloat16 g_Whi[O_ * DP];       // W split-bf16 hi
__device__ __align__(16) __nv_bfloat16 g_Wlo[O_ * DP];       // W split-bf16 lo
__device__ __align__(16) __nv_bfloat16 g_xch[(size_t)NTOT * DP]; // im2col [n][80] hi
__device__ __align__(16) __nv_bfloat16 g_xcl[(size_t)NTOT * DP]; // im2col [n][80] lo
__device__ __align__(16) __nv_bfloat16 g_xunfh[(size_t)D_ * NTOT]; // [d][n] bf16 (rx GEMM)
__device__ __align__(16) __nv_bfloat16 g_rTh[(size_t)O_ * NTOT];   // r^T bf16 [o][n]
__device__ __align__(16) float g_rrP[(size_t)ZB * O_ * O_];  // split-K partials
__device__ __align__(16) float g_rxP[(size_t)ZB * O_ * D_];
__device__ __align__(16) float g_rr[O_ * O_];
__device__ __align__(16) float g_rx[O_ * D_];

// ------------------------- K table + W split prep (merged) ------------------
__global__ void k_init(const float* __restrict__ Wt) {
    int t = blockIdx.x * 256 + threadIdx.x;          // 65536 total
    {   // K table
        int w = t >> 8, o = t & 255;
        int wi = w >> 4, wj = w & 15, i = o >> 4, j = o & 15;
        int a = wi - i + 7, b = wj - j + 7;
        float v = 0.f;
        if (a >= 0 && a < 16 && b >= 0 && b < 16) {
            int da = abs(a - 7), db = abs(b - 7);
            int m = da > db ? da : db;
            v = expf(-(float)(m * m) / 98.0f);
        }
        g_K[t] = v;
    }
    if (t < O_ * DP) {                               // W split-bf16
        int o = t / DP, d = t - o * DP;
        float v = (d < D_) ? Wt[o * D_ + d] : 0.f;
        __nv_bfloat16 hi = __float2bfloat16(v);
        g_Whi[t] = hi;
        g_Wlo[t] = __float2bfloat16(v - __bfloat162float(hi));
    }
}

// ------------------------- tiled im2col (all 3 layouts) ---------------------
// launched in 2 halves (b offset) so k_convfused is launch index 3 for ncu
__global__ void __launch_bounds__(128) k_im2col(const float* __restrict__ x, int bOff) {
    __shared__ float xs[3][5][64];
    int b = bOff + (blockIdx.x >> 6), i = blockIdx.x & 63;   // skip i>=60
    if (i >= HO_) return;
    int tid = threadIdx.x;
    int n0 = b * HW_ + i * WO_;

    for (int idx = tid; idx < 960; idx += 128) {
        int c = idx / 320, rem = idx - c * 320;
        int ki = rem >> 6, col = rem & 63;
        xs[c][ki][col] = x[((b * C_ + c) * H_ + i + ki) * W_ + col];
    }
    __syncthreads();

    for (int u = tid; u < 600; u += 128) {
        int j = u / 10, dblk = (u - j * 10) * 8;
        __nv_bfloat16 hibuf[8], lobuf[8];
#pragma unroll
        for (int dd = 0; dd < 8; dd++) {
            int d = dblk + dd;
            float v = 0.f;
            if (d < D_) {
                int c = d / 25, rr = d - c * 25;
                int ki = rr / 5, kj = rr - ki * 5;
                v = xs[c][ki][j + kj];
            }
            __nv_bfloat16 hi = __float2bfloat16(v);
            hibuf[dd] = hi;
            lobuf[dd] = __float2bfloat16(v - __bfloat162float(hi));
        }
        size_t base = (size_t)(n0 + j) * DP + dblk;
        *(uint4*)(g_xch + base) = *(uint4*)hibuf;
        *(uint4*)(g_xcl + base) = *(uint4*)lobuf;
    }

    for (int u = tid; u < 2250; u += 128) {
        int d = u / 30, j = (u - d * 30) * 2;
        int c = d / 25, rr = d - c * 25;
        int ki = rr / 5, kj = rr - ki * 5;
        __nv_bfloat162 p;
        p.x = __float2bfloat16(xs[c][ki][j + kj]);
        p.y = __float2bfloat16(xs[c][ki][j + 1 + kj]);
        *(__nv_bfloat162*)(g_xunfh + (size_t)d * NTOT + n0 + j) = p;
    }
}

// ------------------------- fused conv + winner + lfb + r --------------------
#define LDSM(r0,r1,r2,r3,addr) \
    asm volatile("ldmatrix.sync.aligned.m8n8.x4.shared.b16 {%0,%1,%2,%3}, [%4];" \
                 : "=r"(r0), "=r"(r1), "=r"(r2), "=r"(r3) : "r"(addr))
#define MMA16816(c0,c1,c2,c3,a0,a1,a2,a3,b0,b1) \
    asm volatile("mma.sync.aligned.m16n8k16.row.col.f32.bf16.bf16.f32 " \
                 "{%0,%1,%2,%3}, {%4,%5,%6,%7}, {%8,%9}, {%0,%1,%2,%3};" \
                 : "+f"(c0), "+f"(c1), "+f"(c2), "+f"(c3) \
                 : "r"(a0), "r"(a1), "r"(a2), "r"(a3), "r"(b0), "r"(b1))

// dyn smem layout: [0,24576) sW ; [24576,30720) sX ; [30720,98304) ybuf/rbuf
#define CF_SMEM 98304

__global__ void __launch_bounds__(256, 2) k_convfused(float* __restrict__ out) {
    extern __shared__ __align__(16) uint8_t dyns[];
    __shared__ float pmax[4][64];
    __shared__ float ymx[64];
    __shared__ int   nbase64[64];
    __shared__ int   cnt[64];
    __shared__ int   widx[64][8];

    __nv_bfloat16* sW = (__nv_bfloat16*)dyns;                   // 512 rows x 24
    __nv_bfloat16* sX = (__nv_bfloat16*)(dyns + 24576);         // 128 rows x 24
    float*         ybuf = (float*)(dyns + 30720);               // 256 rows x 66 fp32
    __nv_bfloat16* rbuf = (__nv_bfloat16*)(dyns + 30720);       // 256 rows x 66 bf16

    int tid = threadIdx.x, lane = tid & 31, wid = tid >> 5;
    int wm = wid >> 1, wn = wid & 1;
    int nT = blockIdx.x * 64;

    uint32_t sWb = (uint32_t)__cvta_generic_to_shared(sW);
    uint32_t sXb = (uint32_t)__cvta_generic_to_shared(sX);

    int lt = lane >> 3, lr = lane & 7;
    int arow = ((lt & 1) << 3) + lr;
    int akch = lt >> 1;

    float c[4][4][4];
#pragma unroll
    for (int i = 0; i < 4; i++)
#pragma unroll
        for (int j = 0; j < 4; j++)
#pragma unroll
            for (int q = 0; q < 4; q++) c[i][j][q] = 0.f;

    int xpiece = tid & 1, xhl = (tid >> 1) & 1, xrow = tid >> 2;

    uint4 wreg[4];
    uint4 xreg;

#pragma unroll
    for (int i = 0; i < 4; i++) {
        int idx = tid + i * 256;
        int row = idx >> 2;
        const __nv_bfloat16* src = ((idx >> 1) & 1) ? g_Wlo : g_Whi;
        wreg[i] = *(const uint4*)(src + row * DP + (idx & 1) * 8);
    }
    {
        const __nv_bfloat16* src = xhl ? g_xcl : g_xch;
        xreg = *(const uint4*)(src + (size_t)(nT + xrow) * DP + xpiece * 8);
    }
#pragma unroll
    for (int i = 0; i < 4; i++) {
        int idx = tid + i * 256;
        int row = idx >> 2;
        *(uint4*)(sW + (((idx >> 1) & 1) * 256 + row) * 24 + (idx & 1) * 8) = wreg[i];
    }
    *(uint4*)(sX + (xhl * 64 + xrow) * 24 + xpiece * 8) = xreg;
    __syncthreads();

    for (int s = 0; s < 5; s++) {
        if (s < 4) {
#pragma unroll
            for (int i = 0; i < 4; i++) {
                int idx = tid + i * 256;
                int row = idx >> 2;
                const __nv_bfloat16* src = ((idx >> 1) & 1) ? g_Wlo : g_Whi;
                wreg[i] = *(const uint4*)(src + row * DP + (s + 1) * 16 + (idx & 1) * 8);
            }
            const __nv_bfloat16* src = xhl ? g_xcl : g_xch;
            xreg = *(const uint4*)(src + (size_t)(nT + xrow) * DP + (s + 1) * 16 + xpiece * 8);
        }

        uint32_t ah[4][4], al[4][4], bh[2][4], bl[2][4];
#pragma unroll
        for (int mi = 0; mi < 4; mi++) {
            int row = wm * 64 + mi * 16 + arow;
            LDSM(ah[mi][0], ah[mi][1], ah[mi][2], ah[mi][3], sWb + row * 48 + akch * 16);
            LDSM(al[mi][0], al[mi][1], al[mi][2], al[mi][3], sWb + (256 + row) * 48 + akch * 16);
        }
#pragma unroll
        for (int bj = 0; bj < 2; bj++) {
            int row = wn * 32 + bj * 16 + arow;
            LDSM(bh[bj][0], bh[bj][1], bh[bj][2], bh[bj][3], sXb + row * 48 + akch * 16);
            LDSM(bl[bj][0], bl[bj][1], bl[bj][2], bl[bj][3], sXb + (64 + row) * 48 + akch * 16);
        }
        // pass-major ordering: 16 independent accumulators between reuses
#pragma unroll
        for (int mi = 0; mi < 4; mi++)
#pragma unroll
            for (int nj = 0; nj < 4; nj++) {
                int g = nj >> 1, od = nj & 1;
                MMA16816(c[mi][nj][0], c[mi][nj][1], c[mi][nj][2], c[mi][nj][3],
                         ah[mi][0], ah[mi][1], ah[mi][2], ah[mi][3],
                         bh[g][od], bh[g][od + 2]);
            }
#pragma unroll
        for (int mi = 0; mi < 4; mi++)
#pragma unroll
            for (int nj = 0; nj < 4; nj++) {
                int g = nj >> 1, od = nj & 1;
                MMA16816(c[mi][nj][0], c[mi][nj][1], c[mi][nj][2], c[mi][nj][3],
                         ah[mi][0], ah[mi][1], ah[mi][2], ah[mi][3],
                         bl[g][od], bl[g][od + 2]);
            }
#pragma unroll
        for (int mi = 0; mi < 4; mi++)
#pragma unroll
            for (int nj = 0; nj < 4; nj++) {
                int g = nj >> 1, od = nj & 1;
                MMA16816(c[mi][nj][0], c[mi][nj][1], c[mi][nj][2], c[mi][nj][3],
                         al[mi][0], al[mi][1], al[mi][2], al[mi][3],
                         bh[g][od], bh[g][od + 2]);
            }
        __syncthreads();
        if (s < 4) {
#pragma unroll
            for (int i = 0; i < 4; i++) {
                int idx = tid + i * 256;
                int row = idx >> 2;
                *(uint4*)(sW + (((idx >> 1) & 1) * 256 + row) * 24 + (idx & 1) * 8) = wreg[i];
            }
            *(uint4*)(sX + (xhl * 64 + xrow) * 24 + xpiece * 8) = xreg;
            __syncthreads();
        }
    }

    // ---------------- epilogue ----------------
    int lq = lane >> 2, ln = lane & 3;

    float tmax[4][2];
#pragma unroll
    for (int nj = 0; nj < 4; nj++)
#pragma unroll
        for (int q = 0; q < 2; q++) tmax[nj][q] = 0.f;
#pragma unroll
    for (int mi = 0; mi < 4; mi++)
#pragma unroll
        for (int nj = 0; nj < 4; nj++)
#pragma unroll
            for (int q = 0; q < 4; q++) {
                float y = fmaxf(c[mi][nj][q], 0.f);
                c[mi][nj][q] = y;
                tmax[nj][q & 1] = fmaxf(tmax[nj][q & 1], y);
            }

#pragma unroll
    for (int nj = 0; nj < 4; nj++)
#pragma unroll
        for (int q = 0; q < 2; q++) {
            float m = tmax[nj][q];
            m = fmaxf(m, __shfl_xor_sync(0xffffffffu, m, 4));
            m = fmaxf(m, __shfl_xor_sync(0xffffffffu, m, 8));
            m = fmaxf(m, __shfl_xor_sync(0xffffffffu, m, 16));
            if (lq == 0) pmax[wm][wn * 32 + nj * 8 + 2 * ln + q] = m;
        }
    if (tid < 64) {
        int n = nT + tid;
        int b = n / HW_;
        nbase64[tid] = b * (O_ * HW_) + (n - b * HW_);
    }
    __syncthreads();

    if (tid < 64) {
        ymx[tid] = fmaxf(fmaxf(pmax[0][tid], pmax[1][tid]),
                         fmaxf(pmax[2][tid], pmax[3][tid]));
        cnt[tid] = 0;
    }
    __syncthreads();

#pragma unroll
    for (int mi = 0; mi < 4; mi++)
#pragma unroll
        for (int h = 0; h < 2; h++) {
            int o = wm * 64 + mi * 16 + lq + 8 * h;
#pragma unroll
            for (int nj = 0; nj < 4; nj++)
#pragma unroll
                for (int q = 0; q < 2; q++) {
                    int nn = wn * 32 + nj * 8 + 2 * ln + q;
                    float ym = ymx[nn];
                    if (ym > 0.f && c[mi][nj][h * 2 + q] == ym) {
                        int pos = atomicAdd(&cnt[nn], 1);
                        if (pos < 8) widx[nn][pos] = o;
                    }
                }
        }

#pragma unroll
    for (int mi = 0; mi < 4; mi++)
#pragma unroll
        for (int h = 0; h < 2; h++) {
            int orow = wm * 64 + mi * 16 + lq + 8 * h;
#pragma unroll
            for (int nj = 0; nj < 4; nj++) {
                int nn = wn * 32 + nj * 8 + 2 * ln;
                ybuf[orow * 66 + nn]     = c[mi][nj][h * 2 + 0];
                ybuf[orow * 66 + nn + 1] = c[mi][nj][h * 2 + 1];
            }
        }
    __syncthreads();

    {
        int hw0 = nT % HW_;
        int b0  = nT / HW_;
        if (hw0 + 64 <= HW_) {                        // fast path: contiguous n
            size_t base = ((size_t)b0 * O_) * HW_ + hw0 + 2 * lane;
#pragma unroll
            for (int rr2 = 0; rr2 < 32; rr2++) {
                int o = wid * 32 + rr2;
                float2 v;
                v.x = ybuf[o * 66 + 2 * lane];
                v.y = ybuf[o * 66 + 2 * lane + 1];
                *(float2*)(out + base + (size_t)o * HW_) = v;
            }
        } else {                                      // batch-boundary block
#pragma unroll
            for (int rr2 = 0; rr2 < 32; rr2++) {
                int o = wid * 32 + rr2;
                size_t ob = (size_t)o * HW_;
                int n0 = 2 * lane;
                out[ob + nbase64[n0]]     = ybuf[o * 66 + n0];
                out[ob + nbase64[n0 + 1]] = ybuf[o * 66 + n0 + 1];
            }
        }
    }
    __syncthreads();

#pragma unroll
    for (int nj = 0; nj < 4; nj++) {
        int nn0 = wn * 32 + nj * 8 + 2 * ln;
#pragma unroll
        for (int mi = 0; mi < 4; mi++)
#pragma unroll
            for (int h = 0; h < 2; h++) {
                int o = wm * 64 + mi * 16 + lq + 8 * h;
                __nv_bfloat162 p;
                p.x = __float2bfloat16(c[mi][nj][h * 2 + 0]);
                p.y = __float2bfloat16(c[mi][nj][h * 2 + 1]);
                *(__nv_bfloat162*)(rbuf + o * 66 + nn0) = p;
            }
    }
    __syncthreads();

    {
        int n = tid & 63, chunk = tid >> 6;          // 64 o per thread
        int cN = min(cnt[n], 8);
#pragma unroll
        for (int sub = 0; sub < 4; sub++) {
            float lfb[16];
#pragma unroll
            for (int i = 0; i < 16; i++) lfb[i] = 0.f;
            for (int j = 0; j < cN; j++) {
                const float4* kp = (const float4*)(g_K + widx[n][j] * O_ + chunk * 64 + sub * 16);
#pragma unroll
                for (int q = 0; q < 4; q++) {
                    float4 kv = kp[q];
                    lfb[q * 4 + 0] += kv.x;
                    lfb[q * 4 + 1] += kv.y;
                    lfb[q * 4 + 2] += kv.z;
                    lfb[q * 4 + 3] += kv.w;
                }
            }
#pragma unroll
            for (int i = 0; i < 16; i++) {
                int o = chunk * 64 + sub * 16 + i;
                float l = fminf(fmaxf(lfb[i], -1.f), 1.f);
                __nv_bfloat16* p = rbuf + o * 66 + n;
                *p = __float2bfloat16(l * __bfloat162float(*p));
            }
        }
    }
    __syncthreads();

#pragma unroll
    for (int rr2 = 0; rr2 < 32; rr2++) {
        int o = wid * 32 + rr2;
        uint32_t v = *(uint32_t*)(rbuf + o * 66 + 2 * lane);
        *(uint32_t*)(g_rTh + (size_t)o * NTOT + nT + 2 * lane) = v;
    }
}

// ------------- merged rr+rx ragged split-K GEMM: 3-stage cp.async -----------
#define CP16(dst, src) \
    asm volatile("cp.async.cg.shared.global [%0], [%1], 16;" :: "r"(dst), "l"(src))
#define CP16Z(dst, src, ss) \
    asm volatile("cp.async.cg.shared.global [%0], [%1], 16, %2;" :: "r"(dst), "l"(src), "r"(ss))
#define CPCOMMIT() asm volatile("cp.async.commit_group;")
#define CPWAIT1()  asm volatile("cp.async.wait_group 1;")

__device__ __forceinline__ uint32_t sw_off(int row, int kch) {
    return (uint32_t)(row * 128 + ((kch ^ (row & 7)) << 4));
}

__global__ void __launch_bounds__(256) k_mma2() {
    extern __shared__ __align__(16) uint8_t dynsm[];

    int t = blockIdx.x;                              // 0..4
    int z = blockIdx.y;                              // 0..ZB-1
    int  mT   = (t == 1 || t == 2 || t == 4) ? 128 : 0;
    bool isRx = (t >= 3);
    bool diag = (t == 0 || t == 2);
    int  nT   = (t == 2) ? 128 : 0;

    int nk = (z < 30) ? 31 : 30;
    size_t kstart = (z < 30) ? (size_t)z * 31 : (size_t)930 + (size_t)(z - 30) * 30;
    size_t k0 = kstart * 64;

    const __nv_bfloat16* A = g_rTh;
    const __nv_bfloat16* Bm = isRx ? g_xunfh : g_rTh;
    float* Cp  = isRx ? (g_rxP + (size_t)z * (O_ * D_))
                      : (g_rrP + (size_t)z * (O_ * O_));
    const int ldc = isRx ? D_ : O_;

    int tid = threadIdx.x;
    int lane = tid & 31, wid = tid >> 5;
    int wm = wid >> 2, wn = wid & 3;

    uint32_t smB = (uint32_t)__cvta_generic_to_shared(dynsm);

    int lrow[4], lch[4];
#pragma unroll
    for (int i = 0; i < 4; i++) {
        int idx = tid + i * 256;
        lrow[i] = idx >> 3;
        lch[i]  = idx & 7;
    }

    float c[4][4][4];
#pragma unroll
    for (int i = 0; i < 4; i++)
#pragma unroll
        for (int j = 0; j < 4; j++)
#pragma unroll
            for (int q = 0; q < 4; q++) c[i][j][q] = 0.f;

    int lt = lane >> 3, lr = lane & 7;
    int arow = ((lt & 1) << 3) + lr;
    int akch = lt >> 1;

    auto issue = [&](int k) {
        int stg = k % 3;
        size_t kb = k0 + (size_t)k * 64;
        uint32_t abase = smB + stg * 32768;
#pragma unroll
        for (int i = 0; i < 4; i++) {
            const void* src = (const void*)(A + (size_t)(mT + lrow[i]) * NTOT + kb + lch[i] * 8);
            CP16(abase + sw_off(lrow[i], lch[i]), src);
        }
        if (!diag) {
            uint32_t bbase = smB + stg * 32768 + 16384;
#pragma unroll
            for (int i = 0; i < 4; i++) {
                int row = lrow[i];
                int grow = isRx ? row : (nT + row);
                int srcrow = (isRx && row >= D_) ? 0 : grow;
                int ss = (isRx && row >= D_) ? 0 : 16;
                const void* src = (const void*)(Bm + (size_t)srcrow * NTOT + kb + lch[i] * 8);
                CP16Z(bbase + sw_off(row, lch[i]), src, ss);
            }
        }
    };

    issue(0); CPCOMMIT();
    issue(1); CPCOMMIT();

    for (int k = 0; k < nk; k++) {
        CPWAIT1();
        __syncthreads();
        if (k + 2 < nk) { issue(k + 2); CPCOMMIT(); }

        uint32_t sA = smB + (k % 3) * 32768;
        uint32_t sB = diag ? sA : sA + 16384;

#pragma unroll
        for (int ks = 0; ks < 4; ks++) {
            int kchb = ks * 2;
            uint32_t af[4][4];
#pragma unroll
            for (int mi = 0; mi < 4; mi++) {
                int row = wm * 64 + mi * 16 + arow;
                LDSM(af[mi][0], af[mi][1], af[mi][2], af[mi][3],
                     sA + sw_off(row, kchb + akch));
            }
            uint32_t bf[2][4];
#pragma unroll
            for (int bj = 0; bj < 2; bj++) {
                int row = wn * 32 + bj * 16 + arow;
                LDSM(bf[bj][0], bf[bj][1], bf[bj][2], bf[bj][3],
                     sB + sw_off(row, kchb + akch));
            }
#pragma unroll
            for (int mi = 0; mi < 4; mi++)
#pragma unroll
                for (int nj = 0; nj < 4; nj++) {
                    int g = nj >> 1, od = nj & 1;
                    MMA16816(c[mi][nj][0], c[mi][nj][1], c[mi][nj][2], c[mi][nj][3],
                             af[mi][0], af[mi][1], af[mi][2], af[mi][3],
                             bf[g][od], bf[g][od + 2]);
                }
        }
    }

#pragma unroll
    for (int mi = 0; mi < 4; mi++) {
        int row0 = mT + wm * 64 + mi * 16 + (lane >> 2);
#pragma unroll
        for (int nj = 0; nj < 4; nj++) {
            int col0 = nT + wn * 32 + nj * 8 + 2 * (lane & 3);
#pragma unroll
            for (int h = 0; h < 2; h++) {
                int r = row0 + h * 8;
                float v0 = c[mi][nj][h * 2 + 0], v1 = c[mi][nj][h * 2 + 1];
                if (!isRx) {
                    Cp[(size_t)r * ldc + col0] = v0;
                    Cp[(size_t)r * ldc + col0 + 1] = v1;
                } else {
                    if (col0 < D_)     Cp[(size_t)r * ldc + col0] = v0;
                    if (col0 + 1 < D_) Cp[(size_t)r * ldc + col0 + 1] = v1;
                }
            }
        }
    }
}

// ------------------------- deterministic split-K reduce ---------------------
__global__ void k_reduce() {
    int t = blockIdx.x * 256 + threadIdx.x;          // 65536 + 19200 = 84736
    if (t < O_ * O_) {
        float s = 0.f;
        for (int z = 0; z < ZB; z++) s += g_rrP[(size_t)z * (O_ * O_) + t];
        g_rr[t] = s;
    } else if (t < O_ * O_ + O_ * D_) {
        int e = t - O_ * O_;
        float s = 0.f;
        for (int z = 0; z < ZB; z++) s += g_rxP[(size_t)z * (O_ * D_) + e];
        g_rx[e] = s;
    }
}

// ------------------------- weight update ------------------------------------
__global__ void k_update(const float* __restrict__ Wt, float* __restrict__ out) {
    int t = blockIdx.x * 256 + threadIdx.x;
    if (t >= O_ * D_) return;
    int o = t / D_;
    int d = t - o * D_;
    float s = 0.f;
    for (int o2 = 0; o2 <= o; o2++)
        s += g_rr[o * O_ + o2] * Wt[o2 * D_ + d];
    out[YOUT + t] = Wt[t] + 0.01f * ((g_rx[t] - s) * (1.0f / 115200.0f));
}

// ---------------------------------------------------------------------------
extern "C" void kernel_launch(void* const* d_in, const int* in_sizes, int n_in,
                              void* d_out, int out_size) {
    const float* x  = (const float*)d_in[0];
    const float* wt = (const float*)d_in[1];
    float* out = (float*)d_out;

    static int smem_set = 0;
    if (!smem_set) {
        cudaFuncSetAttribute(k_mma2, cudaFuncAttributeMaxDynamicSharedMemorySize, 98304);
        cudaFuncSetAttribute(k_convfused, cudaFuncAttributeMaxDynamicSharedMemorySize, CF_SMEM);
        smem_set = 1;
    }

    k_init<<<256, 256>>>(wt);
    k_im2col<<<1024, 128>>>(x, 0);
    k_im2col<<<1024, 128>>>(x, 16);
    k_convfused<<<1800, 256, CF_SMEM>>>(out);     // launch index 3 -> ncu target
    k_mma2<<<dim3(5, ZB), 256, 98304>>>();
    k_reduce<<<332, 256>>>();
    k_update<<<75, 256>>>(wt, out);
}

// round 15
// speedup vs baseline: 1.0474x; 1.0474x over previous
#include <cuda_runtime.h>
#include <cuda_bf16.h>
#include <cstdint>

// ---------------------------------------------------------------------------
// HebbianMap2d: y_out = relu(conv(x,w)); new_w = w + eta*(r^T Xu - tril(r^T r) W)/N
// with r = lfb(winner(relu(s))) * relu(s).
// Shapes: x[32,3,64,64], w[256,3,5,5] -> y_out[32,256,60,60], new_w[256,75]
// NOTE: toolchain targets sm_100 (no 'a') -> tcgen05 unavailable; mma.sync only.
// ---------------------------------------------------------------------------

#define B_    32
#define C_    3
#define H_    64
#define W_    64
#define HO_   60
#define WO_   60
#define HW_   3600          // 60*60
#define O_    256
#define D_    75            // 3*5*5
#define DP    80            // D padded to multiple of 16
#define NTOT  115200        // 32*3600
#define YOUT  29491200      // 32*256*3600
#define ZB    59            // ragged split-K: 30 z's get 31 iters, 29 get 30 (x64)

// ------------------------- scratch (device globals) ------------------------
__device__ __align__(16) float g_K[O_ * O_];                 // SOM lateral kernel
__device__ __align__(16) __nv_bfloat16 g_Whi[O_ * DP];       // W split-bf16 hi
__device__ __align__(16) __nv_bfloat16 g_Wlo[O_ * DP];       // W split-bf16 lo
__device__ __align__(16) __nv_bfloat16 g_xch[(size_t)NTOT * DP]; // im2col [n][80] hi
__device__ __align__(16) __nv_bfloat16 g_xcl[(size_t)NTOT * DP]; // im2col [n][80] lo
__device__ __align__(16) __nv_bfloat16 g_xunfh[(size_t)D_ * NTOT]; // [d][n] bf16 (rx GEMM)
__device__ __align__(16) __nv_bfloat16 g_rTh[(size_t)O_ * NTOT];   // r^T bf16 [o][n]
__device__ __align__(16) float g_rrP[(size_t)ZB * O_ * O_];  // split-K partials
__device__ __align__(16) float g_rxP[(size_t)ZB * O_ * D_];
__device__ __align__(16) float g_rr[O_ * O_];
__device__ __align__(16) float g_rx[O_ * D_];

// ------------------------- K table + W split prep (merged) ------------------
__global__ void k_init(const float* __restrict__ Wt) {
    int t = blockIdx.x * 256 + threadIdx.x;          // 65536 total
    {   // K table
        int w = t >> 8, o = t & 255;
        int wi = w >> 4, wj = w & 15, i = o >> 4, j = o & 15;
        int a = wi - i + 7, b = wj - j + 7;
        float v = 0.f;
        if (a >= 0 && a < 16 && b >= 0 && b < 16) {
            int da = abs(a - 7), db = abs(b - 7);
            int m = da > db ? da : db;
            v = expf(-(float)(m * m) / 98.0f);
        }
        g_K[t] = v;
    }
    if (t < O_ * DP) {                               // W split-bf16
        int o = t / DP, d = t - o * DP;
        float v = (d < D_) ? Wt[o * D_ + d] : 0.f;
        __nv_bfloat16 hi = __float2bfloat16(v);
        g_Whi[t] = hi;
        g_Wlo[t] = __float2bfloat16(v - __bfloat162float(hi));
    }
}

// ------------------------- tiled im2col (all 3 layouts) ---------------------
__global__ void __launch_bounds__(128) k_im2col(const float* __restrict__ x) {
    __shared__ float xs[3][5][64];
    int b = blockIdx.x >> 6, i = blockIdx.x & 63;    // grid 2048, skip i>=60
    if (i >= HO_) return;
    int tid = threadIdx.x;
    int n0 = b * HW_ + i * WO_;

    for (int idx = tid; idx < 960; idx += 128) {
        int c = idx / 320, rem = idx - c * 320;
        int ki = rem >> 6, col = rem & 63;
        xs[c][ki][col] = x[((b * C_ + c) * H_ + i + ki) * W_ + col];
    }
    __syncthreads();

    for (int u = tid; u < 600; u += 128) {
        int j = u / 10, dblk = (u - j * 10) * 8;
        __nv_bfloat16 hibuf[8], lobuf[8];
#pragma unroll
        for (int dd = 0; dd < 8; dd++) {
            int d = dblk + dd;
            float v = 0.f;
            if (d < D_) {
                int c = d / 25, rr = d - c * 25;
                int ki = rr / 5, kj = rr - ki * 5;
                v = xs[c][ki][j + kj];
            }
            __nv_bfloat16 hi = __float2bfloat16(v);
            hibuf[dd] = hi;
            lobuf[dd] = __float2bfloat16(v - __bfloat162float(hi));
        }
        size_t base = (size_t)(n0 + j) * DP + dblk;
        *(uint4*)(g_xch + base) = *(uint4*)hibuf;
        *(uint4*)(g_xcl + base) = *(uint4*)lobuf;
    }

    for (int u = tid; u < 2250; u += 128) {
        int d = u / 30, j = (u - d * 30) * 2;
        int c = d / 25, rr = d - c * 25;
        int ki = rr / 5, kj = rr - ki * 5;
        __nv_bfloat162 p;
        p.x = __float2bfloat16(xs[c][ki][j + kj]);
        p.y = __float2bfloat16(xs[c][ki][j + 1 + kj]);
        *(__nv_bfloat162*)(g_xunfh + (size_t)d * NTOT + n0 + j) = p;
    }
}

// ------------------------- fused conv + winner + lfb + r --------------------
#define LDSM(r0,r1,r2,r3,addr) \
    asm volatile("ldmatrix.sync.aligned.m8n8.x4.shared.b16 {%0,%1,%2,%3}, [%4];" \
                 : "=r"(r0), "=r"(r1), "=r"(r2), "=r"(r3) : "r"(addr))
#define MMA16816(c0,c1,c2,c3,a0,a1,a2,a3,b0,b1) \
    asm volatile("mma.sync.aligned.m16n8k16.row.col.f32.bf16.bf16.f32 " \
                 "{%0,%1,%2,%3}, {%4,%5,%6,%7}, {%8,%9}, {%0,%1,%2,%3};" \
                 : "+f"(c0), "+f"(c1), "+f"(c2), "+f"(c3) \
                 : "r"(a0), "r"(a1), "r"(a2), "r"(a3), "r"(b0), "r"(b1))

// dyn smem layout:
//   [0,24576)       sW (mainloop)      | rbuf 256x68 bf16 (34816 B)  [0,34816)
//   [24576,30720)   sX (mainloop)      |
//   [34816,104448)  ybuf 256x68 fp32 (69632 B)
#define CF_SMEM 104448
#define YB_OFF  34816

__global__ void __launch_bounds__(256, 2) k_convfused(float* __restrict__ out) {
    extern __shared__ __align__(16) uint8_t dyns[];
    __shared__ float pmax[4][64];
    __shared__ float ymx[64];
    __shared__ int   nbase64[64];
    __shared__ int   cnt[64];
    __shared__ int   widx[64][8];

    __nv_bfloat16* sW = (__nv_bfloat16*)dyns;                   // 512 rows x 24
    __nv_bfloat16* sX = (__nv_bfloat16*)(dyns + 24576);         // 128 rows x 24
    __nv_bfloat16* rbuf = (__nv_bfloat16*)dyns;                 // 256 x 68 bf16
    float*         ybuf = (float*)(dyns + YB_OFF);              // 256 x 68 fp32

    int tid = threadIdx.x, lane = tid & 31, wid = tid >> 5;
    int wm = wid >> 1, wn = wid & 1;
    int nT = blockIdx.x * 64;

    uint32_t sWb = (uint32_t)__cvta_generic_to_shared(sW);
    uint32_t sXb = (uint32_t)__cvta_generic_to_shared(sX);

    int lt = lane >> 3, lr = lane & 7;
    int arow = ((lt & 1) << 3) + lr;
    int akch = lt >> 1;

    float c[4][4][4];
#pragma unroll
    for (int i = 0; i < 4; i++)
#pragma unroll
        for (int j = 0; j < 4; j++)
#pragma unroll
            for (int q = 0; q < 4; q++) c[i][j][q] = 0.f;

    int xpiece = tid & 1, xhl = (tid >> 1) & 1, xrow = tid >> 2;

    uint4 wreg[4];
    uint4 xreg;

#pragma unroll
    for (int i = 0; i < 4; i++) {
        int idx = tid + i * 256;
        int row = idx >> 2;
        const __nv_bfloat16* src = ((idx >> 1) & 1) ? g_Wlo : g_Whi;
        wreg[i] = *(const uint4*)(src + row * DP + (idx & 1) * 8);
    }
    {
        const __nv_bfloat16* src = xhl ? g_xcl : g_xch;
        xreg = *(const uint4*)(src + (size_t)(nT + xrow) * DP + xpiece * 8);
    }
#pragma unroll
    for (int i = 0; i < 4; i++) {
        int idx = tid + i * 256;
        int row = idx >> 2;
        *(uint4*)(sW + (((idx >> 1) & 1) * 256 + row) * 24 + (idx & 1) * 8) = wreg[i];
    }
    *(uint4*)(sX + (xhl * 64 + xrow) * 24 + xpiece * 8) = xreg;
    __syncthreads();

    for (int s = 0; s < 5; s++) {
        if (s < 4) {
#pragma unroll
            for (int i = 0; i < 4; i++) {
                int idx = tid + i * 256;
                int row = idx >> 2;
                const __nv_bfloat16* src = ((idx >> 1) & 1) ? g_Wlo : g_Whi;
                wreg[i] = *(const uint4*)(src + row * DP + (s + 1) * 16 + (idx & 1) * 8);
            }
            const __nv_bfloat16* src = xhl ? g_xcl : g_xch;
            xreg = *(const uint4*)(src + (size_t)(nT + xrow) * DP + (s + 1) * 16 + xpiece * 8);
        }

        uint32_t ah[4][4], al[4][4], bh[2][4], bl[2][4];
#pragma unroll
        for (int mi = 0; mi < 4; mi++) {
            int row = wm * 64 + mi * 16 + arow;
            LDSM(ah[mi][0], ah[mi][1], ah[mi][2], ah[mi][3], sWb + row * 48 + akch * 16);
            LDSM(al[mi][0], al[mi][1], al[mi][2], al[mi][3], sWb + (256 + row) * 48 + akch * 16);
        }
#pragma unroll
        for (int bj = 0; bj < 2; bj++) {
            int row = wn * 32 + bj * 16 + arow;
            LDSM(bh[bj][0], bh[bj][1], bh[bj][2], bh[bj][3], sXb + row * 48 + akch * 16);
            LDSM(bl[bj][0], bl[bj][1], bl[bj][2], bl[bj][3], sXb + (64 + row) * 48 + akch * 16);
        }
#pragma unroll
        for (int mi = 0; mi < 4; mi++)
#pragma unroll
            for (int nj = 0; nj < 4; nj++) {
                int g = nj >> 1, od = nj & 1;
                MMA16816(c[mi][nj][0], c[mi][nj][1], c[mi][nj][2], c[mi][nj][3],
                         ah[mi][0], ah[mi][1], ah[mi][2], ah[mi][3],
                         bh[g][od], bh[g][od + 2]);
                MMA16816(c[mi][nj][0], c[mi][nj][1], c[mi][nj][2], c[mi][nj][3],
                         ah[mi][0], ah[mi][1], ah[mi][2], ah[mi][3],
                         bl[g][od], bl[g][od + 2]);
                MMA16816(c[mi][nj][0], c[mi][nj][1], c[mi][nj][2], c[mi][nj][3],
                         al[mi][0], al[mi][1], al[mi][2], al[mi][3],
                         bh[g][od], bh[g][od + 2]);
            }
        __syncthreads();
        if (s < 4) {
#pragma unroll
            for (int i = 0; i < 4; i++) {
                int idx = tid + i * 256;
                int row = idx >> 2;
                *(uint4*)(sW + (((idx >> 1) & 1) * 256 + row) * 24 + (idx & 1) * 8) = wreg[i];
            }
            *(uint4*)(sX + (xhl * 64 + xrow) * 24 + xpiece * 8) = xreg;
            __syncthreads();
        }
    }

    // ---------------- epilogue ----------------
    int lq = lane >> 2, ln = lane & 3;

    // 1) relu in regs + per-thread column max
    float tmax[4][2];
#pragma unroll
    for (int nj = 0; nj < 4; nj++)
#pragma unroll
        for (int q = 0; q < 2; q++) tmax[nj][q] = 0.f;
#pragma unroll
    for (int mi = 0; mi < 4; mi++)
#pragma unroll
        for (int nj = 0; nj < 4; nj++)
#pragma unroll
            for (int q = 0; q < 4; q++) {
                float y = fmaxf(c[mi][nj][q], 0.f);
                c[mi][nj][q] = y;
                tmax[nj][q & 1] = fmaxf(tmax[nj][q & 1], y);
            }

    // 2) warp max -> pmax ; nbase64
#pragma unroll
    for (int nj = 0; nj < 4; nj++)
#pragma unroll
        for (int q = 0; q < 2; q++) {
            float m = tmax[nj][q];
            m = fmaxf(m, __shfl_xor_sync(0xffffffffu, m, 4));
            m = fmaxf(m, __shfl_xor_sync(0xffffffffu, m, 8));
            m = fmaxf(m, __shfl_xor_sync(0xffffffffu, m, 16));
            if (lq == 0) pmax[wm][wn * 32 + nj * 8 + 2 * ln + q] = m;
        }
    if (tid < 64) {
        int n = nT + tid;
        int b = n / HW_;
        nbase64[tid] = b * (O_ * HW_) + (n - b * HW_);
    }
    __syncthreads();

    // 3) combine ymax, reset counters
    if (tid < 64) {
        ymx[tid] = fmaxf(fmaxf(pmax[0][tid], pmax[1][tid]),
                         fmaxf(pmax[2][tid], pmax[3][tid]));
        cnt[tid] = 0;
    }
    __syncthreads();

    // 4) winner detection (from regs)
#pragma unroll
    for (int mi = 0; mi < 4; mi++)
#pragma unroll
        for (int h = 0; h < 2; h++) {
            int o = wm * 64 + mi * 16 + lq + 8 * h;
#pragma unroll
            for (int nj = 0; nj < 4; nj++)
#pragma unroll
                for (int q = 0; q < 2; q++) {
                    int nn = wn * 32 + nj * 8 + 2 * ln + q;
                    float ym = ymx[nn];
                    if (ym > 0.f && c[mi][nj][h * 2 + q] == ym) {
                        int pos = atomicAdd(&cnt[nn], 1);
                        if (pos < 8) widx[nn][pos] = o;
                    }
                }
        }

    // 5) stage y fp32 into ybuf (float2 per write)
#pragma unroll
    for (int mi = 0; mi < 4; mi++)
#pragma unroll
        for (int h = 0; h < 2; h++) {
            int orow = wm * 64 + mi * 16 + lq + 8 * h;
#pragma unroll
            for (int nj = 0; nj < 4; nj++) {
                int nn = wn * 32 + nj * 8 + 2 * ln;
                float2 v;
                v.x = c[mi][nj][h * 2 + 0];
                v.y = c[mi][nj][h * 2 + 1];
                *(float2*)(ybuf + orow * 68 + nn) = v;
            }
        }
    __syncthreads();

    // 6) coalesced y_out write: float4, 2 rows per iter (16 lanes each)
    {
        int hw0 = nT % HW_;
        int b0  = nT / HW_;
        int half = lane >> 4, j = lane & 15;          // j: float4 index in row
        if (hw0 + 64 <= HW_) {                        // fast path: contiguous n
            size_t base = ((size_t)b0 * O_) * HW_ + hw0 + 4 * j;
#pragma unroll
            for (int rr2 = 0; rr2 < 16; rr2++) {
                int o = wid * 32 + rr2 * 2 + half;
                float4 v = *(float4*)(ybuf + o * 68 + 4 * j);
                *(float4*)(out + base + (size_t)o * HW_) = v;
            }
        } else {                                      // batch-boundary block
#pragma unroll
            for (int rr2 = 0; rr2 < 32; rr2++) {
                int o = wid * 32 + rr2;
                size_t ob = (size_t)o * HW_;
                int n0 = 2 * lane;
                out[ob + nbase64[n0]]     = ybuf[o * 68 + n0];
                out[ob + nbase64[n0 + 1]] = ybuf[o * 68 + n0 + 1];
            }
        }
    }

    // 7) lfb per (n, chunk): read y from ybuf (fp32), write r to rbuf (bf16)
    //    (no sync needed: reads ybuf written before sync 5->6; rbuf region dead)
    {
        int n = tid & 63, chunk = tid >> 6;          // 64 o per thread
        int cN = min(cnt[n], 8);
#pragma unroll
        for (int sub = 0; sub < 4; sub++) {
            float lfb[16];
#pragma unroll
            for (int i = 0; i < 16; i++) lfb[i] = 0.f;
            for (int j = 0; j < cN; j++) {
                const float4* kp = (const float4*)(g_K + widx[n][j] * O_ + chunk * 64 + sub * 16);
#pragma unroll
                for (int q = 0; q < 4; q++) {
                    float4 kv = kp[q];
                    lfb[q * 4 + 0] += kv.x;
                    lfb[q * 4 + 1] += kv.y;
                    lfb[q * 4 + 2] += kv.z;
                    lfb[q * 4 + 3] += kv.w;
                }
            }
#pragma unroll
            for (int i = 0; i < 16; i++) {
                int o = chunk * 64 + sub * 16 + i;
                float l = fminf(fmaxf(lfb[i], -1.f), 1.f);
                rbuf[o * 68 + n] = __float2bfloat16(l * ybuf[o * 68 + n]);
            }
        }
    }
    __syncthreads();

    // 8) coalesced rT write
#pragma unroll
    for (int rr2 = 0; rr2 < 32; rr2++) {
        int o = wid * 32 + rr2;
        uint32_t v = *(uint32_t*)(rbuf + o * 68 + 2 * lane);
        *(uint32_t*)(g_rTh + (size_t)o * NTOT + nT + 2 * lane) = v;
    }
}

// ------------- merged rr+rx ragged split-K GEMM: 3-stage cp.async -----------
#define CP16(dst, src) \
    asm volatile("cp.async.cg.shared.global [%0], [%1], 16;" :: "r"(dst), "l"(src))
#define CP16Z(dst, src, ss) \
    asm volatile("cp.async.cg.shared.global [%0], [%1], 16, %2;" :: "r"(dst), "l"(src), "r"(ss))
#define CPCOMMIT() asm volatile("cp.async.commit_group;")
#define CPWAIT1()  asm volatile("cp.async.wait_group 1;")

__device__ __forceinline__ uint32_t sw_off(int row, int kch) {
    return (uint32_t)(row * 128 + ((kch ^ (row & 7)) << 4));
}

__global__ void __launch_bounds__(256) k_mma2() {
    extern __shared__ __align__(16) uint8_t dynsm[];

    int t = blockIdx.x;                              // 0..4
    int z = blockIdx.y;                              // 0..ZB-1
    int  mT   = (t == 1 || t == 2 || t == 4) ? 128 : 0;
    bool isRx = (t >= 3);
    bool diag = (t == 0 || t == 2);
    int  nT   = (t == 2) ? 128 : 0;

    int nk = (z < 30) ? 31 : 30;
    size_t kstart = (z < 30) ? (size_t)z * 31 : (size_t)930 + (size_t)(z - 30) * 30;
    size_t k0 = kstart * 64;

    const __nv_bfloat16* A = g_rTh;
    const __nv_bfloat16* Bm = isRx ? g_xunfh : g_rTh;
    float* Cp  = isRx ? (g_rxP + (size_t)z * (O_ * D_))
                      : (g_rrP + (size_t)z * (O_ * O_));
    const int ldc = isRx ? D_ : O_;

    int tid = threadIdx.x;
    int lane = tid & 31, wid = tid >> 5;
    int wm = wid >> 2, wn = wid & 3;

    uint32_t smB = (uint32_t)__cvta_generic_to_shared(dynsm);

    int lrow[4], lch[4];
#pragma unroll
    for (int i = 0; i < 4; i++) {
        int idx = tid + i * 256;
        lrow[i] = idx >> 3;
        lch[i]  = idx & 7;
    }

    float c[4][4][4];
#pragma unroll
    for (int i = 0; i < 4; i++)
#pragma unroll
        for (int j = 0; j < 4; j++)
#pragma unroll
            for (int q = 0; q < 4; q++) c[i][j][q] = 0.f;

    int lt = lane >> 3, lr = lane & 7;
    int arow = ((lt & 1) << 3) + lr;
    int akch = lt >> 1;

    auto issue = [&](int k) {
        int stg = k % 3;
        size_t kb = k0 + (size_t)k * 64;
        uint32_t abase = smB + stg * 32768;
#pragma unroll
        for (int i = 0; i < 4; i++) {
            const void* src = (const void*)(A + (size_t)(mT + lrow[i]) * NTOT + kb + lch[i] * 8);
            CP16(abase + sw_off(lrow[i], lch[i]), src);
        }
        if (!diag) {
            uint32_t bbase = smB + stg * 32768 + 16384;
#pragma unroll
            for (int i = 0; i < 4; i++) {
                int row = lrow[i];
                int grow = isRx ? row : (nT + row);
                int srcrow = (isRx && row >= D_) ? 0 : grow;
                int ss = (isRx && row >= D_) ? 0 : 16;
                const void* src = (const void*)(Bm + (size_t)srcrow * NTOT + kb + lch[i] * 8);
                CP16Z(bbase + sw_off(row, lch[i]), src, ss);
            }
        }
    };

    issue(0); CPCOMMIT();
    issue(1); CPCOMMIT();

    for (int k = 0; k < nk; k++) {
        CPWAIT1();
        __syncthreads();
        if (k + 2 < nk) { issue(k + 2); CPCOMMIT(); }

        uint32_t sA = smB + (k % 3) * 32768;
        uint32_t sB = diag ? sA : sA + 16384;

#pragma unroll
        for (int ks = 0; ks < 4; ks++) {
            int kchb = ks * 2;
            uint32_t af[4][4];
#pragma unroll
            for (int mi = 0; mi < 4; mi++) {
                int row = wm * 64 + mi * 16 + arow;
                LDSM(af[mi][0], af[mi][1], af[mi][2], af[mi][3],
                     sA + sw_off(row, kchb + akch));
            }
            uint32_t bf[2][4];
#pragma unroll
            for (int bj = 0; bj < 2; bj++) {
                int row = wn * 32 + bj * 16 + arow;
                LDSM(bf[bj][0], bf[bj][1], bf[bj][2], bf[bj][3],
                     sB + sw_off(row, kchb + akch));
            }
#pragma unroll
            for (int mi = 0; mi < 4; mi++)
#pragma unroll
                for (int nj = 0; nj < 4; nj++) {
                    int g = nj >> 1, od = nj & 1;
                    MMA16816(c[mi][nj][0], c[mi][nj][1], c[mi][nj][2], c[mi][nj][3],
                             af[mi][0], af[mi][1], af[mi][2], af[mi][3],
                             bf[g][od], bf[g][od + 2]);
                }
        }
    }

#pragma unroll
    for (int mi = 0; mi < 4; mi++) {
        int row0 = mT + wm * 64 + mi * 16 + (lane >> 2);
#pragma unroll
        for (int nj = 0; nj < 4; nj++) {
            int col0 = nT + wn * 32 + nj * 8 + 2 * (lane & 3);
#pragma unroll
            for (int h = 0; h < 2; h++) {
                int r = row0 + h * 8;
                float v0 = c[mi][nj][h * 2 + 0], v1 = c[mi][nj][h * 2 + 1];
                if (!isRx) {
                    Cp[(size_t)r * ldc + col0] = v0;
                    Cp[(size_t)r * ldc + col0 + 1] = v1;
                } else {
                    if (col0 < D_)     Cp[(size_t)r * ldc + col0] = v0;
                    if (col0 + 1 < D_) Cp[(size_t)r * ldc + col0 + 1] = v1;
                }
            }
        }
    }
}

// ------------------------- deterministic split-K reduce ---------------------
__global__ void k_reduce() {
    int t = blockIdx.x * 256 + threadIdx.x;          // 65536 + 19200 = 84736
    if (t < O_ * O_) {
        float s = 0.f;
        for (int z = 0; z < ZB; z++) s += g_rrP[(size_t)z * (O_ * O_) + t];
        g_rr[t] = s;
    } else if (t < O_ * O_ + O_ * D_) {
        int e = t - O_ * O_;
        float s = 0.f;
        for (int z = 0; z < ZB; z++) s += g_rxP[(size_t)z * (O_ * D_) + e];
        g_rx[e] = s;
    }
}

// ------------------------- weight update ------------------------------------
__global__ void k_update(const float* __restrict__ Wt, float* __restrict__ out) {
    int t = blockIdx.x * 256 + threadIdx.x;
    if (t >= O_ * D_) return;
    int o = t / D_;
    int d = t - o * D_;
    float s = 0.f;
    for (int o2 = 0; o2 <= o; o2++)
        s += g_rr[o * O_ + o2] * Wt[o2 * D_ + d];
    out[YOUT + t] = Wt[t] + 0.01f * ((g_rx[t] - s) * (1.0f / 115200.0f));
}

// ---------------------------------------------------------------------------
extern "C" void kernel_launch(void* const* d_in, const int* in_sizes, int n_in,
                              void* d_out, int out_size) {
    const float* x  = (const float*)d_in[0];
    const float* wt = (const float*)d_in[1];
    float* out = (float*)d_out;

    static int smem_set = 0;
    if (!smem_set) {
        cudaFuncSetAttribute(k_mma2, cudaFuncAttributeMaxDynamicSharedMemorySize, 98304);
        cudaFuncSetAttribute(k_convfused, cudaFuncAttributeMaxDynamicSharedMemorySize, CF_SMEM);
        smem_set = 1;
    }

    k_init<<<256, 256>>>(wt);
    k_im2col<<<2048, 128>>>(x);
    k_convfused<<<1800, 256, CF_SMEM>>>(out);
    k_mma2<<<dim3(5, ZB), 256, 98304>>>();
    k_reduce<<<332, 256>>>();
    k_update<<<75, 256>>>(wt, out);
}

// round 16
// speedup vs baseline: 1.1068x; 1.0568x over previous
#include <cuda_runtime.h>
#include <cuda_bf16.h>
#include <cstdint>

// ---------------------------------------------------------------------------
// HebbianMap2d: y_out = relu(conv(x,w)); new_w = w + eta*(r^T Xu - tril(r^T r) W)/N
// with r = lfb(winner(relu(s))) * relu(s).
// Shapes: x[32,3,64,64], w[256,3,5,5] -> y_out[32,256,60,60], new_w[256,75]
// NOTE: toolchain targets sm_100 (no 'a') -> tcgen05 unavailable; mma.sync only.
// ---------------------------------------------------------------------------

#define B_    32
#define C_    3
#define H_    64
#define W_    64
#define HO_   60
#define WO_   60
#define HW_   3600          // 60*60
#define O_    256
#define D_    75            // 3*5*5
#define DP    80            // D padded to multiple of 16
#define NTOT  115200        // 32*3600
#define YOUT  29491200      // 32*256*3600
#define ZB    59            // ragged split-K: 30 z's get 31 iters, 29 get 30 (x64)

// ------------------------- scratch (device globals) ------------------------
__device__ __align__(16) float g_K[O_ * O_];                 // SOM lateral kernel
__device__ __align__(16) __nv_bfloat16 g_Whi[O_ * DP];       // W split-bf16 hi
__device__ __align__(16) __nv_bfloat16 g_Wlo[O_ * DP];       // W split-bf16 lo
__device__ __align__(16) __nv_bfloat16 g_xch[(size_t)NTOT * DP]; // im2col [n][80] hi
__device__ __align__(16) __nv_bfloat16 g_xcl[(size_t)NTOT * DP]; // im2col [n][80] lo
__device__ __align__(16) __nv_bfloat16 g_xunfh[(size_t)D_ * NTOT]; // [d][n] bf16 (rx GEMM)
__device__ __align__(16) __nv_bfloat16 g_rTh[(size_t)O_ * NTOT];   // r^T bf16 [o][n]
__device__ __align__(16) float g_rrP[(size_t)ZB * O_ * O_];  // split-K partials
__device__ __align__(16) float g_rxP[(size_t)ZB * O_ * D_];
__device__ __align__(16) float g_rr[O_ * O_];
__device__ __align__(16) float g_rx[O_ * D_];

// ------------------------- K table + W split prep (merged) ------------------
__global__ void k_init(const float* __restrict__ Wt) {
    int t = blockIdx.x * 256 + threadIdx.x;          // 65536 total
    {   // K table
        int w = t >> 8, o = t & 255;
        int wi = w >> 4, wj = w & 15, i = o >> 4, j = o & 15;
        int a = wi - i + 7, b = wj - j + 7;
        float v = 0.f;
        if (a >= 0 && a < 16 && b >= 0 && b < 16) {
            int da = abs(a - 7), db = abs(b - 7);
            int m = da > db ? da : db;
            v = expf(-(float)(m * m) / 98.0f);
        }
        g_K[t] = v;
    }
    if (t < O_ * DP) {                               // W split-bf16
        int o = t / DP, d = t - o * DP;
        float v = (d < D_) ? Wt[o * D_ + d] : 0.f;
        __nv_bfloat16 hi = __float2bfloat16(v);
        g_Whi[t] = hi;
        g_Wlo[t] = __float2bfloat16(v - __bfloat162float(hi));
    }
}

// ------------------------- tiled im2col (all 3 layouts) ---------------------
__global__ void __launch_bounds__(128) k_im2col(const float* __restrict__ x) {
    __shared__ float xs[3][5][64];
    int b = blockIdx.x >> 6, i = blockIdx.x & 63;    // grid 2048, skip i>=60
    if (i >= HO_) return;
    int tid = threadIdx.x;
    int n0 = b * HW_ + i * WO_;

    for (int idx = tid; idx < 960; idx += 128) {
        int c = idx / 320, rem = idx - c * 320;
        int ki = rem >> 6, col = rem & 63;
        xs[c][ki][col] = x[((b * C_ + c) * H_ + i + ki) * W_ + col];
    }
    __syncthreads();

    for (int u = tid; u < 600; u += 128) {
        int j = u / 10, dblk = (u - j * 10) * 8;
        __nv_bfloat16 hibuf[8], lobuf[8];
#pragma unroll
        for (int dd = 0; dd < 8; dd++) {
            int d = dblk + dd;
            float v = 0.f;
            if (d < D_) {
                int c = d / 25, rr = d - c * 25;
                int ki = rr / 5, kj = rr - ki * 5;
                v = xs[c][ki][j + kj];
            }
            __nv_bfloat16 hi = __float2bfloat16(v);
            hibuf[dd] = hi;
            lobuf[dd] = __float2bfloat16(v - __bfloat162float(hi));
        }
        size_t base = (size_t)(n0 + j) * DP + dblk;
        *(uint4*)(g_xch + base) = *(uint4*)hibuf;
        *(uint4*)(g_xcl + base) = *(uint4*)lobuf;
    }

    for (int u = tid; u < 2250; u += 128) {
        int d = u / 30, j = (u - d * 30) * 2;
        int c = d / 25, rr = d - c * 25;
        int ki = rr / 5, kj = rr - ki * 5;
        __nv_bfloat162 p;
        p.x = __float2bfloat16(xs[c][ki][j + kj]);
        p.y = __float2bfloat16(xs[c][ki][j + 1 + kj]);
        *(__nv_bfloat162*)(g_xunfh + (size_t)d * NTOT + n0 + j) = p;
    }
}

// ------------------------- common PTX macros --------------------------------
#define LDSM(r0,r1,r2,r3,addr) \
    asm volatile("ldmatrix.sync.aligned.m8n8.x4.shared.b16 {%0,%1,%2,%3}, [%4];" \
                 : "=r"(r0), "=r"(r1), "=r"(r2), "=r"(r3) : "r"(addr))
#define MMA16816(c0,c1,c2,c3,a0,a1,a2,a3,b0,b1) \
    asm volatile("mma.sync.aligned.m16n8k16.row.col.f32.bf16.bf16.f32 " \
                 "{%0,%1,%2,%3}, {%4,%5,%6,%7}, {%8,%9}, {%0,%1,%2,%3};" \
                 : "+f"(c0), "+f"(c1), "+f"(c2), "+f"(c3) \
                 : "r"(a0), "r"(a1), "r"(a2), "r"(a3), "r"(b0), "r"(b1))
#define CP16(dst, src) \
    asm volatile("cp.async.cg.shared.global [%0], [%1], 16;" :: "r"(dst), "l"(src))
#define CP16Z(dst, src, ss) \
    asm volatile("cp.async.cg.shared.global [%0], [%1], 16, %2;" :: "r"(dst), "l"(src), "r"(ss))
#define CPCOMMIT() asm volatile("cp.async.commit_group;")
#define CPWAIT1()  asm volatile("cp.async.wait_group 1;")
#define CPWAIT0()  asm volatile("cp.async.wait_group 0;")

// ------------------------- fused conv + winner + lfb + r --------------------
// dyn smem layout:
//   mainloop: 3 stages x (sW 24576 + sX 6144) = 92160 at [0,92160)
//   epilogue: rbuf 256x68 bf16 [0,34816) ; ybuf 256x68 fp32 [34816,104448)
#define CF_SMEM 104448
#define CF_STG  30720
#define YB_OFF  34816

__global__ void __launch_bounds__(256, 2) k_convfused(float* __restrict__ out) {
    extern __shared__ __align__(16) uint8_t dyns[];
    __shared__ float pmax[4][64];
    __shared__ float ymx[64];
    __shared__ int   nbase64[64];
    __shared__ int   cnt[64];
    __shared__ int   widx[64][8];

    __nv_bfloat16* rbuf = (__nv_bfloat16*)dyns;                 // 256 x 68 bf16
    float*         ybuf = (float*)(dyns + YB_OFF);              // 256 x 68 fp32

    int tid = threadIdx.x, lane = tid & 31, wid = tid >> 5;
    int wm = wid >> 1, wn = wid & 1;
    int nT = blockIdx.x * 64;

    uint32_t smB = (uint32_t)__cvta_generic_to_shared(dyns);

    int lt = lane >> 3, lr = lane & 7;
    int arow = ((lt & 1) << 3) + lr;
    int akch = lt >> 1;

    float c[4][4][4];
#pragma unroll
    for (int i = 0; i < 4; i++)
#pragma unroll
        for (int j = 0; j < 4; j++)
#pragma unroll
            for (int q = 0; q < 4; q++) c[i][j][q] = 0.f;

    int xpiece = tid & 1, xhl = (tid >> 1) & 1, xrow = tid >> 2;

    // cp.async stage issue (no registers consumed for data)
    auto issue = [&](int s) {
        uint32_t base = smB + (s % 3) * CF_STG;
#pragma unroll
        for (int i = 0; i < 4; i++) {
            int idx = tid + i * 256;
            int row = idx >> 2, hl = (idx >> 1) & 1, piece = idx & 1;
            const __nv_bfloat16* src =
                (hl ? g_Wlo : g_Whi) + row * DP + s * 16 + piece * 8;
            CP16(base + (hl * 256 + row) * 48 + piece * 16, (const void*)src);
        }
        const __nv_bfloat16* src =
            (xhl ? g_xcl : g_xch) + (size_t)(nT + xrow) * DP + s * 16 + xpiece * 8;
        CP16(base + 24576 + (xhl * 64 + xrow) * 48 + xpiece * 16, (const void*)src);
    };

    issue(0); CPCOMMIT();
    issue(1); CPCOMMIT();

    for (int s = 0; s < 5; s++) {
        if (s < 4) CPWAIT1(); else CPWAIT0();        // stage s landed
        __syncthreads();
        if (s + 2 < 5) { issue(s + 2); CPCOMMIT(); } // writes buf (s-1)%3: safe

        uint32_t sWb = smB + (s % 3) * CF_STG;
        uint32_t sXb = sWb + 24576;

        uint32_t ah[4][4], al[4][4], bh[2][4], bl[2][4];
#pragma unroll
        for (int mi = 0; mi < 4; mi++) {
            int row = wm * 64 + mi * 16 + arow;
            LDSM(ah[mi][0], ah[mi][1], ah[mi][2], ah[mi][3], sWb + row * 48 + akch * 16);
            LDSM(al[mi][0], al[mi][1], al[mi][2], al[mi][3], sWb + (256 + row) * 48 + akch * 16);
        }
#pragma unroll
        for (int bj = 0; bj < 2; bj++) {
            int row = wn * 32 + bj * 16 + arow;
            LDSM(bh[bj][0], bh[bj][1], bh[bj][2], bh[bj][3], sXb + row * 48 + akch * 16);
            LDSM(bl[bj][0], bl[bj][1], bl[bj][2], bl[bj][3], sXb + (64 + row) * 48 + akch * 16);
        }
#pragma unroll
        for (int mi = 0; mi < 4; mi++)
#pragma unroll
            for (int nj = 0; nj < 4; nj++) {
                int g = nj >> 1, od = nj & 1;
                MMA16816(c[mi][nj][0], c[mi][nj][1], c[mi][nj][2], c[mi][nj][3],
                         ah[mi][0], ah[mi][1], ah[mi][2], ah[mi][3],
                         bh[g][od], bh[g][od + 2]);
                MMA16816(c[mi][nj][0], c[mi][nj][1], c[mi][nj][2], c[mi][nj][3],
                         ah[mi][0], ah[mi][1], ah[mi][2], ah[mi][3],
                         bl[g][od], bl[g][od + 2]);
                MMA16816(c[mi][nj][0], c[mi][nj][1], c[mi][nj][2], c[mi][nj][3],
                         al[mi][0], al[mi][1], al[mi][2], al[mi][3],
                         bh[g][od], bh[g][od + 2]);
            }
    }

    // ---------------- epilogue ----------------
    int lq = lane >> 2, ln = lane & 3;

    // 1) relu in regs + per-thread column max
    float tmax[4][2];
#pragma unroll
    for (int nj = 0; nj < 4; nj++)
#pragma unroll
        for (int q = 0; q < 2; q++) tmax[nj][q] = 0.f;
#pragma unroll
    for (int mi = 0; mi < 4; mi++)
#pragma unroll
        for (int nj = 0; nj < 4; nj++)
#pragma unroll
            for (int q = 0; q < 4; q++) {
                float y = fmaxf(c[mi][nj][q], 0.f);
                c[mi][nj][q] = y;
                tmax[nj][q & 1] = fmaxf(tmax[nj][q & 1], y);
            }

    // 2) warp max -> pmax ; nbase64
#pragma unroll
    for (int nj = 0; nj < 4; nj++)
#pragma unroll
        for (int q = 0; q < 2; q++) {
            float m = tmax[nj][q];
            m = fmaxf(m, __shfl_xor_sync(0xffffffffu, m, 4));
            m = fmaxf(m, __shfl_xor_sync(0xffffffffu, m, 8));
            m = fmaxf(m, __shfl_xor_sync(0xffffffffu, m, 16));
            if (lq == 0) pmax[wm][wn * 32 + nj * 8 + 2 * ln + q] = m;
        }
    if (tid < 64) {
        int n = nT + tid;
        int b = n / HW_;
        nbase64[tid] = b * (O_ * HW_) + (n - b * HW_);
    }
    __syncthreads();

    // 3) combine ymax, reset counters
    if (tid < 64) {
        ymx[tid] = fmaxf(fmaxf(pmax[0][tid], pmax[1][tid]),
                         fmaxf(pmax[2][tid], pmax[3][tid]));
        cnt[tid] = 0;
    }
    __syncthreads();

    // 4) winner detection (from regs)
#pragma unroll
    for (int mi = 0; mi < 4; mi++)
#pragma unroll
        for (int h = 0; h < 2; h++) {
            int o = wm * 64 + mi * 16 + lq + 8 * h;
#pragma unroll
            for (int nj = 0; nj < 4; nj++)
#pragma unroll
                for (int q = 0; q < 2; q++) {
                    int nn = wn * 32 + nj * 8 + 2 * ln + q;
                    float ym = ymx[nn];
                    if (ym > 0.f && c[mi][nj][h * 2 + q] == ym) {
                        int pos = atomicAdd(&cnt[nn], 1);
                        if (pos < 8) widx[nn][pos] = o;
                    }
                }
        }

    // 5) stage y fp32 into ybuf (float2 per write)
#pragma unroll
    for (int mi = 0; mi < 4; mi++)
#pragma unroll
        for (int h = 0; h < 2; h++) {
            int orow = wm * 64 + mi * 16 + lq + 8 * h;
#pragma unroll
            for (int nj = 0; nj < 4; nj++) {
                int nn = wn * 32 + nj * 8 + 2 * ln;
                float2 v;
                v.x = c[mi][nj][h * 2 + 0];
                v.y = c[mi][nj][h * 2 + 1];
                *(float2*)(ybuf + orow * 68 + nn) = v;
            }
        }
    __syncthreads();

    // 6) coalesced y_out write: float4, 2 rows per iter (16 lanes each)
    {
        int hw0 = nT % HW_;
        int b0  = nT / HW_;
        int half = lane >> 4, j = lane & 15;          // j: float4 index in row
        if (hw0 + 64 <= HW_) {                        // fast path: contiguous n
            size_t base = ((size_t)b0 * O_) * HW_ + hw0 + 4 * j;
#pragma unroll
            for (int rr2 = 0; rr2 < 16; rr2++) {
                int o = wid * 32 + rr2 * 2 + half;
                float4 v = *(float4*)(ybuf + o * 68 + 4 * j);
                *(float4*)(out + base + (size_t)o * HW_) = v;
            }
        } else {                                      // batch-boundary block
#pragma unroll
            for (int rr2 = 0; rr2 < 32; rr2++) {
                int o = wid * 32 + rr2;
                size_t ob = (size_t)o * HW_;
                int n0 = 2 * lane;
                out[ob + nbase64[n0]]     = ybuf[o * 68 + n0];
                out[ob + nbase64[n0 + 1]] = ybuf[o * 68 + n0 + 1];
            }
        }
    }

    // 7) lfb per (n, chunk): read y from ybuf (fp32), write r to rbuf (bf16)
    {
        int n = tid & 63, chunk = tid >> 6;          // 64 o per thread
        int cN = min(cnt[n], 8);
#pragma unroll
        for (int sub = 0; sub < 4; sub++) {
            float lfb[16];
#pragma unroll
            for (int i = 0; i < 16; i++) lfb[i] = 0.f;
            for (int j = 0; j < cN; j++) {
                const float4* kp = (const float4*)(g_K + widx[n][j] * O_ + chunk * 64 + sub * 16);
#pragma unroll
                for (int q = 0; q < 4; q++) {
                    float4 kv = kp[q];
                    lfb[q * 4 + 0] += kv.x;
                    lfb[q * 4 + 1] += kv.y;
                    lfb[q * 4 + 2] += kv.z;
                    lfb[q * 4 + 3] += kv.w;
                }
            }
#pragma unroll
            for (int i = 0; i < 16; i++) {
                int o = chunk * 64 + sub * 16 + i;
                float l = fminf(fmaxf(lfb[i], -1.f), 1.f);
                rbuf[o * 68 + n] = __float2bfloat16(l * ybuf[o * 68 + n]);
            }
        }
    }
    __syncthreads();

    // 8) coalesced rT write
#pragma unroll
    for (int rr2 = 0; rr2 < 32; rr2++) {
        int o = wid * 32 + rr2;
        uint32_t v = *(uint32_t*)(rbuf + o * 68 + 2 * lane);
        *(uint32_t*)(g_rTh + (size_t)o * NTOT + nT + 2 * lane) = v;
    }
}

// ------------- merged rr+rx ragged split-K GEMM: 3-stage cp.async -----------
__device__ __forceinline__ uint32_t sw_off(int row, int kch) {
    return (uint32_t)(row * 128 + ((kch ^ (row & 7)) << 4));
}

__global__ void __launch_bounds__(256) k_mma2() {
    extern __shared__ __align__(16) uint8_t dynsm[];

    int t = blockIdx.x;                              // 0..4
    int z = blockIdx.y;                              // 0..ZB-1
    int  mT   = (t == 1 || t == 2 || t == 4) ? 128 : 0;
    bool isRx = (t >= 3);
    bool diag = (t == 0 || t == 2);
    int  nT   = (t == 2) ? 128 : 0;

    int nk = (z < 30) ? 31 : 30;
    size_t kstart = (z < 30) ? (size_t)z * 31 : (size_t)930 + (size_t)(z - 30) * 30;
    size_t k0 = kstart * 64;

    const __nv_bfloat16* A = g_rTh;
    const __nv_bfloat16* Bm = isRx ? g_xunfh : g_rTh;
    float* Cp  = isRx ? (g_rxP + (size_t)z * (O_ * D_))
                      : (g_rrP + (size_t)z * (O_ * O_));
    const int ldc = isRx ? D_ : O_;

    int tid = threadIdx.x;
    int lane = tid & 31, wid = tid >> 5;
    int wm = wid >> 2, wn = wid & 3;

    uint32_t smB = (uint32_t)__cvta_generic_to_shared(dynsm);

    int lrow[4], lch[4];
#pragma unroll
    for (int i = 0; i < 4; i++) {
        int idx = tid + i * 256;
        lrow[i] = idx >> 3;
        lch[i]  = idx & 7;
    }

    float c[4][4][4];
#pragma unroll
    for (int i = 0; i < 4; i++)
#pragma unroll
        for (int j = 0; j < 4; j++)
#pragma unroll
            for (int q = 0; q < 4; q++) c[i][j][q] = 0.f;

    int lt = lane >> 3, lr = lane & 7;
    int arow = ((lt & 1) << 3) + lr;
    int akch = lt >> 1;

    auto issue = [&](int k) {
        int stg = k % 3;
        size_t kb = k0 + (size_t)k * 64;
        uint32_t abase = smB + stg * 32768;
#pragma unroll
        for (int i = 0; i < 4; i++) {
            const void* src = (const void*)(A + (size_t)(mT + lrow[i]) * NTOT + kb + lch[i] * 8);
            CP16(abase + sw_off(lrow[i], lch[i]), src);
        }
        if (!diag) {
            uint32_t bbase = smB + stg * 32768 + 16384;
#pragma unroll
            for (int i = 0; i < 4; i++) {
                int row = lrow[i];
                int grow = isRx ? row : (nT + row);
                int srcrow = (isRx && row >= D_) ? 0 : grow;
                int ss = (isRx && row >= D_) ? 0 : 16;
                const void* src = (const void*)(Bm + (size_t)srcrow * NTOT + kb + lch[i] * 8);
                CP16Z(bbase + sw_off(row, lch[i]), src, ss);
            }
        }
    };

    issue(0); CPCOMMIT();
    issue(1); CPCOMMIT();

    for (int k = 0; k < nk; k++) {
        if (k < nk - 1) CPWAIT1(); else CPWAIT0();   // stage k landed (guaranteed)
        __syncthreads();
        if (k + 2 < nk) { issue(k + 2); CPCOMMIT(); }

        uint32_t sA = smB + (k % 3) * 32768;
        uint32_t sB = diag ? sA : sA + 16384;

#pragma unroll
        for (int ks = 0; ks < 4; ks++) {
            int kchb = ks * 2;
            uint32_t af[4][4];
#pragma unroll
            for (int mi = 0; mi < 4; mi++) {
                int row = wm * 64 + mi * 16 + arow;
                LDSM(af[mi][0], af[mi][1], af[mi][2], af[mi][3],
                     sA + sw_off(row, kchb + akch));
            }
            uint32_t bf[2][4];
#pragma unroll
            for (int bj = 0; bj < 2; bj++) {
                int row = wn * 32 + bj * 16 + arow;
                LDSM(bf[bj][0], bf[bj][1], bf[bj][2], bf[bj][3],
                     sB + sw_off(row, kchb + akch));
            }
#pragma unroll
            for (int mi = 0; mi < 4; mi++)
#pragma unroll
                for (int nj = 0; nj < 4; nj++) {
                    int g = nj >> 1, od = nj & 1;
                    MMA16816(c[mi][nj][0], c[mi][nj][1], c[mi][nj][2], c[mi][nj][3],
                             af[mi][0], af[mi][1], af[mi][2], af[mi][3],
                             bf[g][od], bf[g][od + 2]);
                }
        }
    }

#pragma unroll
    for (int mi = 0; mi < 4; mi++) {
        int row0 = mT + wm * 64 + mi * 16 + (lane >> 2);
#pragma unroll
        for (int nj = 0; nj < 4; nj++) {
            int col0 = nT + wn * 32 + nj * 8 + 2 * (lane & 3);
#pragma unroll
            for (int h = 0; h < 2; h++) {
                int r = row0 + h * 8;
                float v0 = c[mi][nj][h * 2 + 0], v1 = c[mi][nj][h * 2 + 1];
                if (!isRx) {
                    Cp[(size_t)r * ldc + col0] = v0;
                    Cp[(size_t)r * ldc + col0 + 1] = v1;
                } else {
                    if (col0 < D_)     Cp[(size_t)r * ldc + col0] = v0;
                    if (col0 + 1 < D_) Cp[(size_t)r * ldc + col0 + 1] = v1;
                }
            }
        }
    }
}

// ------------------------- deterministic split-K reduce ---------------------
__global__ void k_reduce() {
    int t = blockIdx.x * 256 + threadIdx.x;          // 65536 + 19200 = 84736
    if (t < O_ * O_) {
        float s = 0.f;
        for (int z = 0; z < ZB; z++) s += g_rrP[(size_t)z * (O_ * O_) + t];
        g_rr[t] = s;
    } else if (t < O_ * O_ + O_ * D_) {
        int e = t - O_ * O_;
        float s = 0.f;
        for (int z = 0; z < ZB; z++) s += g_rxP[(size_t)z * (O_ * D_) + e];
        g_rx[e] = s;
    }
}

// ------------------------- weight update ------------------------------------
__global__ void k_update(const float* __restrict__ Wt, float* __restrict__ out) {
    int t = blockIdx.x * 256 + threadIdx.x;
    if (t >= O_ * D_) return;
    int o = t / D_;
    int d = t - o * D_;
    float s = 0.f;
    for (int o2 = 0; o2 <= o; o2++)
        s += g_rr[o * O_ + o2] * Wt[o2 * D_ + d];
    out[YOUT + t] = Wt[t] + 0.01f * ((g_rx[t] - s) * (1.0f / 115200.0f));
}

// ---------------------------------------------------------------------------
extern "C" void kernel_launch(void* const* d_in, const int* in_sizes, int n_in,
                              void* d_out, int out_size) {
    const float* x  = (const float*)d_in[0];
    const float* wt = (const float*)d_in[1];
    float* out = (float*)d_out;

    static int smem_set = 0;
    if (!smem_set) {
        cudaFuncSetAttribute(k_mma2, cudaFuncAttributeMaxDynamicSharedMemorySize, 98304);
        cudaFuncSetAttribute(k_convfused, cudaFuncAttributeMaxDynamicSharedMemorySize, CF_SMEM);
        smem_set = 1;
    }

    k_init<<<256, 256>>>(wt);
    k_im2col<<<2048, 128>>>(x);
    k_convfused<<<1800, 256, CF_SMEM>>>(out);
    k_mma2<<<dim3(5, ZB), 256, 98304>>>();
    k_reduce<<<332, 256>>>();
    k_update<<<75, 256>>>(wt, out);
}